// round 1
// baseline (speedup 1.0000x reference)
#include <cuda_runtime.h>

// Shapes: field/gt_field (8,4,64,128,64) f32, ct/gt_ct (8,1) f32, sdf (8,1,64,128,64) f32.
// Output: scalar f32 total loss.

#define NB 8
#define ND 64
#define NH 128
#define NW 64
#define SP (ND*NH*NW)          // 524288  spatial per (batch,channel)
#define CS SP                   // channel stride
#define NPTS (NB*SP)            // 4194304 spatial points total

// grid-step constants (match reference double->f32 path)
#define DXd ((2.0 + 0.5) / 63.0)
#define DYd ((0.5 + 0.5) / 127.0)
#define DZd ((0.3 + 0.5) / 63.0)

__device__ __constant__ float c_inv2dx = (float)(1.0 / (2.0 * DXd));
__device__ __constant__ float c_inv2dy = (float)(1.0 / (2.0 * DYd));
__device__ __constant__ float c_inv2dz = (float)(1.0 / (2.0 * DZd));
__device__ __constant__ float c_idx2   = (float)(1.0 / (DXd * DXd));
__device__ __constant__ float c_idy2   = (float)(1.0 / (DYd * DYd));
__device__ __constant__ float c_idz2   = (float)(1.0 / (DZd * DZd));

// per-term weight / count scales
__device__ __constant__ float c_sc_field  = (float)(1.0  / (double)(NB*4*SP));     // L_FIELD=1
__device__ __constant__ float c_sc_ct     = (float)(10.0 / 8.0);                    // L_CT=10
__device__ __constant__ float c_sc_cont   = (float)(1.0  / (double)(NB*(ND-2)*(NH-2)*(NW-2)));
__device__ __constant__ float c_sc_mom    = (float)(1.0  / (double)(NB*(ND-2)*(NH-2)*(NW-2)));
__device__ __constant__ float c_sc_noslip = (float)(10.0 / (double)NPTS);
__device__ __constant__ float c_sc_inlet  = (float)(5.0  / (double)(NB*ND*NH));
__device__ __constant__ float c_sc_outlet = (float)(1.0  / (double)(NB*ND*NH));

#define INV_RE 1.0e-6f

__device__ double g_acc;

__global__ void k_zero() { g_acc = 0.0; }

__global__ void __launch_bounds__(256) k_loss(
    const float* __restrict__ field,
    const float* __restrict__ ct,
    const float* __restrict__ gt_field,
    const float* __restrict__ gt_ct,
    const float* __restrict__ sdf)
{
    const int gid = blockIdx.x * 256 + threadIdx.x;   // exactly NPTS threads
    const int w = gid & (NW - 1);
    const int h = (gid >> 6) & (NH - 1);
    const int d = (gid >> 13) & (ND - 1);
    const int b = gid >> 19;

    float acc = 0.0f;

    // ct loss (8 elements) handled by first 8 threads
    if (gid < 8) {
        float dct = ct[gid] - gt_ct[gid];
        acc += c_sc_ct * dct * dct;
    }

    const int sidx  = (d * NH + h) * NW + w;
    const int fbase = b * (4 * SP) + sidx;
    const float* fb = field + fbase;
    const float* gb = gt_field + fbase;

    // center values, all 4 channels
    const float u  = fb[0];
    const float v  = fb[CS];
    const float wv = fb[2 * CS];
    const float p  = fb[3 * CS];

    // field MSE
    {
        float a0 = u  - gb[0];
        float a1 = v  - gb[CS];
        float a2 = wv - gb[2 * CS];
        float a3 = p  - gb[3 * CS];
        acc += c_sc_field * (a0 * a0 + a1 * a1 + a2 * a2 + a3 * a3);
    }

    const float s = sdf[b * SP + sidx];

    // no-slip on solid (sdf <= 0), full grid
    if (s <= 0.0f)
        acc += c_sc_noslip * (u * u + v * v + wv * wv);

    // inlet plane w == 0
    if (w == 0) {
        float du0 = u - 1.0f;   // U_INF = 1
        acc += c_sc_inlet * (du0 * du0 + v * v + wv * wv);
    }

    // outlet plane w == NW-1 vs NW-2
    if (w == NW - 1) {
        float a0 = u  - fb[-1];
        float a1 = v  - fb[CS - 1];
        float a2 = wv - fb[2 * CS - 1];
        acc += c_sc_outlet * (a0 * a0 + a1 * a1 + a2 * a2);
    }

    // interior: continuity + momentum (gated by fluid mask)
    if (w >= 1 && w <= NW - 2 && h >= 1 && h <= NH - 2 && d >= 1 && d <= ND - 2) {
        if (s > 0.0f) {
            // x: +-1 (W), y: +-NW (H), z: +-NH*NW (D)
            const int OY = NW;
            const int OZ = NH * NW;

            float uxp = fb[1],        uxm = fb[-1];
            float uyp = fb[OY],       uym = fb[-OY];
            float uzp = fb[OZ],       uzm = fb[-OZ];

            float vxp = fb[CS + 1],   vxm = fb[CS - 1];
            float vyp = fb[CS + OY],  vym = fb[CS - OY];
            float vzp = fb[CS + OZ],  vzm = fb[CS - OZ];

            float wxp = fb[2*CS + 1],  wxm = fb[2*CS - 1];
            float wyp = fb[2*CS + OY], wym = fb[2*CS - OY];
            float wzp = fb[2*CS + OZ], wzm = fb[2*CS - OZ];

            float pxp = fb[3*CS + 1],  pxm = fb[3*CS - 1];
            float pyp = fb[3*CS + OY], pym = fb[3*CS - OY];
            float pzp = fb[3*CS + OZ], pzm = fb[3*CS - OZ];

            float du_dx = (uxp - uxm) * c_inv2dx;
            float du_dy = (uyp - uym) * c_inv2dy;
            float du_dz = (uzp - uzm) * c_inv2dz;

            float dv_dx = (vxp - vxm) * c_inv2dx;
            float dv_dy = (vyp - vym) * c_inv2dy;
            float dv_dz = (vzp - vzm) * c_inv2dz;

            float dw_dx = (wxp - wxm) * c_inv2dx;
            float dw_dy = (wyp - wym) * c_inv2dy;
            float dw_dz = (wzp - wzm) * c_inv2dz;

            float dp_dx = (pxp - pxm) * c_inv2dx;
            float dp_dy = (pyp - pym) * c_inv2dy;
            float dp_dz = (pzp - pzm) * c_inv2dz;

            float div = du_dx + dv_dy + dw_dz;
            acc += c_sc_cont * div * div;

            float lap_u = (uxp - 2.0f * u  + uxm) * c_idx2
                        + (uyp - 2.0f * u  + uym) * c_idy2
                        + (uzp - 2.0f * u  + uzm) * c_idz2;
            float lap_v = (vxp - 2.0f * v  + vxm) * c_idx2
                        + (vyp - 2.0f * v  + vym) * c_idy2
                        + (vzp - 2.0f * v  + vzm) * c_idz2;
            float lap_w = (wxp - 2.0f * wv + wxm) * c_idx2
                        + (wyp - 2.0f * wv + wym) * c_idy2
                        + (wzp - 2.0f * wv + wzm) * c_idz2;

            float rx = u * du_dx + v * du_dy + wv * du_dz + dp_dx - INV_RE * lap_u;
            float ry = u * dv_dx + v * dv_dy + wv * dv_dz + dp_dy - INV_RE * lap_v;
            float rz = u * dw_dx + v * dw_dy + wv * dw_dz + dp_dz - INV_RE * lap_w;

            acc += c_sc_mom * (rx * rx + ry * ry + rz * rz);
        }
    }

    // ---- reduction: warp shfl (f32) -> block (f64) -> global atomic (f64) ----
    #pragma unroll
    for (int o = 16; o > 0; o >>= 1)
        acc += __shfl_down_sync(0xffffffffu, acc, o);

    __shared__ double warpsum[8];
    if ((threadIdx.x & 31) == 0)
        warpsum[threadIdx.x >> 5] = (double)acc;
    __syncthreads();

    if (threadIdx.x < 8) {
        double t = warpsum[threadIdx.x];
        #pragma unroll
        for (int o = 4; o > 0; o >>= 1)
            t += __shfl_down_sync(0x000000ffu, t, o);
        if (threadIdx.x == 0)
            atomicAdd(&g_acc, t);
    }
}

__global__ void k_fin(float* __restrict__ out) {
    out[0] = (float)g_acc;
}

extern "C" void kernel_launch(void* const* d_in, const int* in_sizes, int n_in,
                              void* d_out, int out_size)
{
    const float* field    = (const float*)d_in[0];
    const float* ct       = (const float*)d_in[1];
    const float* gt_field = (const float*)d_in[2];
    const float* gt_ct    = (const float*)d_in[3];
    const float* sdf      = (const float*)d_in[4];

    k_zero<<<1, 1>>>();
    k_loss<<<NPTS / 256, 256>>>(field, ct, gt_field, gt_ct, sdf);
    k_fin<<<1, 1>>>((float*)d_out);
}